// round 13
// baseline (speedup 1.0000x reference)
#include <cuda_runtime.h>
#include <cuda_bf16.h>
#include <cooperative_groups.h>
#include <cstdint>

namespace cg = cooperative_groups;

// EfficientReynoldsFeatureOperator:
//   x:  (B=8, N=8192, D=512) fp32
//   W:  (512, 128) fp32, pw: (128) fp32
//   out:(B, N, R) fp32,  out[b,n,r] = (mean_n(x[b]) @ W)[r] * pw[r]
// Using mean_n(x @ W) == (mean_n x) @ W.
//
// Session ledger: k1 read ceiling 5.8 TB/s (proven across configs), k3 store
// wall ~3.7 TB/s (proven across STG/ILP/TMA), kernel time ~33.6us inside a
// 38.9us wall -> ~5us of launch gaps. This round: ONE cooperative kernel,
// grid.sync() between phases (hw barrier ~0.26us), 1024 blocks (co-resident
// at launch_bounds(128,8): 148 SMs x 8 = 1184 >= 1024).

#define B_DIM 8
#define N_DIM 8192
#define D_DIM 512
#define R_DIM 128
#define CHUNKS 128                            // chunks per batch (1024 blocks)
#define ROWS_PER_CHUNK (N_DIM / CHUNKS)       // 64
#define NJ 32                                 // d-slices for projection
#define SLICE_D (D_DIM / NJ)                  // 16
#define NBLK (B_DIM * CHUNKS)                 // 1024

__device__ float g_partial[B_DIM * CHUNKS * D_DIM];   // 2 MB (L2-hot)
__device__ float g_yp[B_DIM * NJ * R_DIM];            // 128 KB partial y's

// ---------------------------------------------------------------------------
// Phase 1: block (b, chunk) sums 64 rows of x. Proven MLP-8 __ldcs body.
// ---------------------------------------------------------------------------
__device__ __forceinline__ void phase1(const float* __restrict__ x, int bid, int t) {
    const int b     = bid >> 7;
    const int chunk = bid & 127;

    const float4* xrow = reinterpret_cast<const float4*>(
        x + ((size_t)b * N_DIM + (size_t)chunk * ROWS_PER_CHUNK) * D_DIM);

    float4 a0 = make_float4(0.f, 0.f, 0.f, 0.f);
    float4 a1 = make_float4(0.f, 0.f, 0.f, 0.f);

#pragma unroll
    for (int i = 0; i < ROWS_PER_CHUNK; i += 8) {
        float4 v0 = __ldcs(&xrow[(size_t)(i + 0) * 128 + t]);
        float4 v1 = __ldcs(&xrow[(size_t)(i + 1) * 128 + t]);
        float4 v2 = __ldcs(&xrow[(size_t)(i + 2) * 128 + t]);
        float4 v3 = __ldcs(&xrow[(size_t)(i + 3) * 128 + t]);
        float4 v4 = __ldcs(&xrow[(size_t)(i + 4) * 128 + t]);
        float4 v5 = __ldcs(&xrow[(size_t)(i + 5) * 128 + t]);
        float4 v6 = __ldcs(&xrow[(size_t)(i + 6) * 128 + t]);
        float4 v7 = __ldcs(&xrow[(size_t)(i + 7) * 128 + t]);
        a0.x += v0.x; a0.y += v0.y; a0.z += v0.z; a0.w += v0.w;
        a1.x += v1.x; a1.y += v1.y; a1.z += v1.z; a1.w += v1.w;
        a0.x += v2.x; a0.y += v2.y; a0.z += v2.z; a0.w += v2.w;
        a1.x += v3.x; a1.y += v3.y; a1.z += v3.z; a1.w += v3.w;
        a0.x += v4.x; a0.y += v4.y; a0.z += v4.z; a0.w += v4.w;
        a1.x += v5.x; a1.y += v5.y; a1.z += v5.z; a1.w += v5.w;
        a0.x += v6.x; a0.y += v6.y; a0.z += v6.z; a0.w += v6.w;
        a1.x += v7.x; a1.y += v7.y; a1.z += v7.z; a1.w += v7.w;
    }
    a0.x += a1.x; a0.y += a1.y; a0.z += a1.z; a0.w += a1.w;

    float4* p = reinterpret_cast<float4*>(
        g_partial + ((size_t)b * CHUNKS + chunk) * D_DIM);
    p[t] = a0;
}

// ---------------------------------------------------------------------------
// Phase 2 (blocks 0..255): block (b=bid>>5, j=bid&31) owns d-slice [16j,16j+16).
// Reduce slice over 128 chunks (coalesced, L2-hot), project through 16 W rows.
// ---------------------------------------------------------------------------
__device__ __forceinline__ void phase2(const float* __restrict__ W,
                                       const float* __restrict__ pw,
                                       int bid, int t) {
    __shared__ float4 red[128];
    __shared__ float  s_mean[SLICE_D];
    const int j = bid & 31;
    const int b = bid >> 5;
    const int q    = t & 3;           // float4 within 16-d slice
    const int lane = t >> 2;          // 0..31 chunk lane

    const float4* p4 = reinterpret_cast<const float4*>(g_partial)
                     + (size_t)b * CHUNKS * 128;

    float4 acc = make_float4(0.f, 0.f, 0.f, 0.f);
#pragma unroll
    for (int k = 0; k < 4; ++k) {                   // 128 chunks / 32 lanes
        const int c = lane + 32 * k;
        float4 v = __ldcg(&p4[(size_t)c * 128 + j * 4 + q]);
        acc.x += v.x; acc.y += v.y; acc.z += v.z; acc.w += v.w;
    }
    red[t] = acc;
    __syncthreads();

#pragma unroll
    for (int off = 16; off >= 1; off >>= 1) {
        if (lane < off) {
            float4 o = red[q + 4 * (lane + off)];
            float4 m = red[q + 4 * lane];
            m.x += o.x; m.y += o.y; m.z += o.z; m.w += o.w;
            red[q + 4 * lane] = m;
        }
        __syncthreads();
    }
    if (t < 4) {
        const float invN = 1.0f / (float)N_DIM;
        float4 m = red[t];
        s_mean[4 * t + 0] = m.x * invN;
        s_mean[4 * t + 1] = m.y * invN;
        s_mean[4 * t + 2] = m.z * invN;
        s_mean[4 * t + 3] = m.w * invN;
    }
    __syncthreads();

    float acc_r = 0.f;
#pragma unroll
    for (int dd = 0; dd < SLICE_D; ++dd)
        acc_r = fmaf(s_mean[dd], __ldg(&W[(size_t)(j * SLICE_D + dd) * R_DIM + t]), acc_r);

    g_yp[((size_t)b * NJ + j) * R_DIM + t] = acc_r * __ldg(&pw[t]);
}

// ---------------------------------------------------------------------------
// Phase 3: block (b=bid>>7, seg=bid&127) sums the 32 y-partials (hot 128 KB)
// then streams its 32 KB output segment (16 coalesced STG.128 per thread).
// ---------------------------------------------------------------------------
__device__ __forceinline__ void phase3(float4* __restrict__ out4, int bid, int t) {
    const int b   = bid >> 7;
    const int seg = bid & 127;
    const int c4  = t & 31;

    const float4* yp4 = reinterpret_cast<const float4*>(g_yp)
                      + (size_t)b * NJ * (R_DIM / 4);

    float4 s0 = make_float4(0.f, 0.f, 0.f, 0.f);
    float4 s1 = make_float4(0.f, 0.f, 0.f, 0.f);
    float4 s2 = make_float4(0.f, 0.f, 0.f, 0.f);
    float4 s3 = make_float4(0.f, 0.f, 0.f, 0.f);
#pragma unroll
    for (int jj = 0; jj < NJ; jj += 4) {
        float4 u0 = __ldg(&yp4[(size_t)(jj + 0) * 32 + c4]);
        float4 u1 = __ldg(&yp4[(size_t)(jj + 1) * 32 + c4]);
        float4 u2 = __ldg(&yp4[(size_t)(jj + 2) * 32 + c4]);
        float4 u3 = __ldg(&yp4[(size_t)(jj + 3) * 32 + c4]);
        s0.x += u0.x; s0.y += u0.y; s0.z += u0.z; s0.w += u0.w;
        s1.x += u1.x; s1.y += u1.y; s1.z += u1.z; s1.w += u1.w;
        s2.x += u2.x; s2.y += u2.y; s2.z += u2.z; s2.w += u2.w;
        s3.x += u3.x; s3.y += u3.y; s3.z += u3.z; s3.w += u3.w;
    }
    s0.x += s1.x; s0.y += s1.y; s0.z += s1.z; s0.w += s1.w;
    s2.x += s3.x; s2.y += s3.y; s2.z += s3.z; s2.w += s3.w;
    float4 v;
    v.x = s0.x + s2.x; v.y = s0.y + s2.y; v.z = s0.z + s2.z; v.w = s0.w + s2.w;

    float4* dst = out4 + (size_t)b * (N_DIM * R_DIM / 4) + (size_t)seg * 2048;
#pragma unroll
    for (int i = 0; i < 16; ++i)
        dst[(size_t)i * 128 + t] = v;
}

// ---------------------------------------------------------------------------
// Fused cooperative kernel: all three phases, hardware grid barriers between.
// ---------------------------------------------------------------------------
__global__ __launch_bounds__(128, 8) void fused_coop(
    const float* __restrict__ x, const float* __restrict__ W,
    const float* __restrict__ pw, float4* __restrict__ out4) {
    cg::grid_group grid = cg::this_grid();
    phase1(x, blockIdx.x, threadIdx.x);
    grid.sync();
    if (blockIdx.x < B_DIM * NJ)
        phase2(W, pw, blockIdx.x, threadIdx.x);
    grid.sync();
    phase3(out4, blockIdx.x, threadIdx.x);
}

// Fallback (non-cooperative): same phases as 3 launches.
__global__ __launch_bounds__(128, 8) void kA(const float* __restrict__ x) {
    phase1(x, blockIdx.x, threadIdx.x);
}
__global__ __launch_bounds__(128) void kB(const float* __restrict__ W,
                                          const float* __restrict__ pw) {
    phase2(W, pw, blockIdx.x, threadIdx.x);
}
__global__ __launch_bounds__(128) void kC(float4* __restrict__ out4) {
    phase3(out4, blockIdx.x, threadIdx.x);
}

// ---------------------------------------------------------------------------
extern "C" void kernel_launch(void* const* d_in, const int* in_sizes, int n_in,
                              void* d_out, int out_size) {
    const float* x  = (const float*)d_in[0];
    const float* W  = (const float*)d_in[1];
    const float* pw = (const float*)d_in[2];
    float4* out4    = (float4*)d_out;

    (void)in_sizes; (void)n_in; (void)out_size;

    // Cooperative path requires full co-residency of all NBLK blocks.
    int dev = 0;
    cudaGetDevice(&dev);
    int coop = 0, sms = 0, perSM = 0;
    cudaDeviceGetAttribute(&coop, cudaDevAttrCooperativeLaunch, dev);
    cudaDeviceGetAttribute(&sms, cudaDevAttrMultiProcessorCount, dev);
    cudaOccupancyMaxActiveBlocksPerMultiprocessor(&perSM, fused_coop, 128, 0);

    if (coop && (size_t)perSM * sms >= NBLK) {
        void* args[] = {(void*)&x, (void*)&W, (void*)&pw, (void*)&out4};
        cudaLaunchCooperativeKernel((void*)fused_coop, dim3(NBLK), dim3(128),
                                    args, 0, (cudaStream_t)0);
    } else {
        kA<<<NBLK, 128>>>(x);
        kB<<<B_DIM * NJ, 128>>>(W, pw);
        kC<<<NBLK, 128>>>(out4);
    }
}

// round 15
// speedup vs baseline: 1.1224x; 1.1224x over previous
#include <cuda_runtime.h>
#include <cuda_bf16.h>
#include <cstdint>

// EfficientReynoldsFeatureOperator:
//   x:  (B=8, N=8192, D=512) fp32
//   W:  (512, 128) fp32, pw: (128) fp32
//   out:(B, N, R) fp32,  out[b,n,r] = (mean_n(x[b]) @ W)[r] * pw[r]
// Using mean_n(x @ W) == (mean_n x) @ W.
//
// Round-5 proven bodies (best 38.66us) chained with Programmatic Dependent
// Launch: successors carry programmaticStreamSerialization and begin with
// cudaGridDependencySynchronize(), overlapping launch ramps with the
// predecessor's tail. (Round-14 bench died with the Round-0 infra signature
// before compiling; resubmitting.)

#define B_DIM 8
#define N_DIM 8192
#define D_DIM 512
#define R_DIM 128
#define CHUNKS 256
#define ROWS_PER_CHUNK (N_DIM / CHUNKS)     // 32
#define G2 32                                // k2a blocks per batch
#define CHUNKS_PER_G2 (CHUNKS / G2)          // 8

__device__ float g_partial[B_DIM * CHUNKS * D_DIM];   // 4 MB scratch (L2-hot)
__device__ float g_p2[B_DIM * G2 * D_DIM];            // 512 KB
__device__ float g_y[B_DIM * R_DIM];                  // 4 KB

// ---------------------------------------------------------------------------
// K1: partial column sums of x over n. (proven 5.8 TB/s body)
// grid = (CHUNKS, B) = 2048 blocks, 128 threads.
// ---------------------------------------------------------------------------
__global__ __launch_bounds__(128, 8) void k1_colsum_partial(const float* __restrict__ x) {
    const int chunk = blockIdx.x;
    const int b     = blockIdx.y;
    const int t     = threadIdx.x;            // 0..127

    const float4* xrow = reinterpret_cast<const float4*>(
        x + ((size_t)b * N_DIM + (size_t)chunk * ROWS_PER_CHUNK) * D_DIM);

    float4 a0 = make_float4(0.f, 0.f, 0.f, 0.f);
    float4 a1 = make_float4(0.f, 0.f, 0.f, 0.f);

#pragma unroll
    for (int i = 0; i < ROWS_PER_CHUNK; i += 8) {
        float4 v0 = __ldcs(&xrow[(size_t)(i + 0) * 128 + t]);
        float4 v1 = __ldcs(&xrow[(size_t)(i + 1) * 128 + t]);
        float4 v2 = __ldcs(&xrow[(size_t)(i + 2) * 128 + t]);
        float4 v3 = __ldcs(&xrow[(size_t)(i + 3) * 128 + t]);
        float4 v4 = __ldcs(&xrow[(size_t)(i + 4) * 128 + t]);
        float4 v5 = __ldcs(&xrow[(size_t)(i + 5) * 128 + t]);
        float4 v6 = __ldcs(&xrow[(size_t)(i + 6) * 128 + t]);
        float4 v7 = __ldcs(&xrow[(size_t)(i + 7) * 128 + t]);
        a0.x += v0.x; a0.y += v0.y; a0.z += v0.z; a0.w += v0.w;
        a1.x += v1.x; a1.y += v1.y; a1.z += v1.z; a1.w += v1.w;
        a0.x += v2.x; a0.y += v2.y; a0.z += v2.z; a0.w += v2.w;
        a1.x += v3.x; a1.y += v3.y; a1.z += v3.z; a1.w += v3.w;
        a0.x += v4.x; a0.y += v4.y; a0.z += v4.z; a0.w += v4.w;
        a1.x += v5.x; a1.y += v5.y; a1.z += v5.z; a1.w += v5.w;
        a0.x += v6.x; a0.y += v6.y; a0.z += v6.z; a0.w += v6.w;
        a1.x += v7.x; a1.y += v7.y; a1.z += v7.z; a1.w += v7.w;
    }
    a0.x += a1.x; a0.y += a1.y; a0.z += a1.z; a0.w += a1.w;

    float4* p = reinterpret_cast<float4*>(
        g_partial + ((size_t)b * CHUNKS + chunk) * D_DIM);
    p[t] = a0;

    cudaTriggerProgrammaticLaunchCompletion();
}

// ---------------------------------------------------------------------------
// K2a: first-level partial reduction, 256 blocks. (round-5 body + PDL)
// ---------------------------------------------------------------------------
__global__ __launch_bounds__(128) void k2a_reduce(void) {
    const int j  = blockIdx.x;
    const int b  = blockIdx.y;
    const int d4 = threadIdx.x;

    cudaGridDependencySynchronize();            // wait for k1's stores

    const float4* base = reinterpret_cast<const float4*>(
        g_partial + ((size_t)b * CHUNKS + (size_t)j * CHUNKS_PER_G2) * D_DIM);

    float4 acc = make_float4(0.f, 0.f, 0.f, 0.f);
#pragma unroll
    for (int c = 0; c < CHUNKS_PER_G2; ++c) {
        float4 v = base[(size_t)c * 128 + d4];
        acc.x += v.x; acc.y += v.y; acc.z += v.z; acc.w += v.w;
    }
    float4* p = reinterpret_cast<float4*>(
        g_p2 + ((size_t)b * G2 + j) * D_DIM);
    p[d4] = acc;

    cudaTriggerProgrammaticLaunchCompletion();
}

// ---------------------------------------------------------------------------
// K2b: per batch finish + projection. grid = B, 512 thr. (round-5 body + PDL)
// ---------------------------------------------------------------------------
__global__ __launch_bounds__(512) void k2b_finish_and_project(
    const float* __restrict__ W, const float* __restrict__ pw) {
    __shared__ float s_part[4][D_DIM];
    __shared__ float s_mean[D_DIM];
    __shared__ float s_red[16][R_DIM];
    const int b = blockIdx.x;
    const int t = threadIdx.x;
    const int g  = t >> 7;        // 0..3
    const int d4 = t & 127;       // 0..127

    cudaGridDependencySynchronize();            // wait for k2a's stores

    const float4* pbase = reinterpret_cast<const float4*>(
        g_p2 + (size_t)b * G2 * D_DIM);

    float4 acc = make_float4(0.f, 0.f, 0.f, 0.f);
#pragma unroll
    for (int c = g; c < G2; c += 4) {
        float4 v = pbase[(size_t)c * 128 + d4];
        acc.x += v.x; acc.y += v.y; acc.z += v.z; acc.w += v.w;
    }
    s_part[g][4 * d4 + 0] = acc.x;
    s_part[g][4 * d4 + 1] = acc.y;
    s_part[g][4 * d4 + 2] = acc.z;
    s_part[g][4 * d4 + 3] = acc.w;
    __syncthreads();

    s_mean[t] = (s_part[0][t] + s_part[1][t] + s_part[2][t] + s_part[3][t])
                * (1.0f / (float)N_DIM);
    __syncthreads();

    const int w    = t >> 5;
    const int lane = t & 31;
    float p0 = 0.f, p1 = 0.f, p2 = 0.f, p3 = 0.f;
#pragma unroll
    for (int i = 0; i < 32; ++i) {
        const int d = w * 32 + i;
        const float m = s_mean[d];
        const float* Wr = W + (size_t)d * R_DIM;
        p0 = fmaf(m, __ldg(&Wr[lane]),      p0);
        p1 = fmaf(m, __ldg(&Wr[32 + lane]), p1);
        p2 = fmaf(m, __ldg(&Wr[64 + lane]), p2);
        p3 = fmaf(m, __ldg(&Wr[96 + lane]), p3);
    }
    s_red[w][lane]      = p0;
    s_red[w][32 + lane] = p1;
    s_red[w][64 + lane] = p2;
    s_red[w][96 + lane] = p3;
    __syncthreads();

    if (t < R_DIM) {
        float y = 0.f;
#pragma unroll
        for (int k = 0; k < 16; ++k)
            y += s_red[k][t];
        g_y[b * R_DIM + t] = y * pw[t];
    }

    cudaTriggerProgrammaticLaunchCompletion();
}

// ---------------------------------------------------------------------------
// K3: broadcast y. (round-5 proven 8-ILP body + PDL)
// ---------------------------------------------------------------------------
__global__ __launch_bounds__(256) void k3_broadcast(float4* __restrict__ out) {
    const int tid = blockIdx.x * blockDim.x + threadIdx.x;  // 0..262143
    const int r4  = tid & (R_DIM / 4 - 1);

    cudaGridDependencySynchronize();            // wait for k2b's g_y stores

    const float4* y4 = reinterpret_cast<const float4*>(g_y);
#pragma unroll
    for (int b = 0; b < B_DIM; ++b) {
        float4 v = __ldg(&y4[b * (R_DIM / 4) + r4]);
        out[(size_t)b * (N_DIM * R_DIM / 4) + tid] = v;
    }
}

// ---------------------------------------------------------------------------
extern "C" void kernel_launch(void* const* d_in, const int* in_sizes, int n_in,
                              void* d_out, int out_size) {
    const float* x  = (const float*)d_in[0];
    const float* W  = (const float*)d_in[1];
    const float* pw = (const float*)d_in[2];
    float4* out4    = (float4*)d_out;

    (void)in_sizes; (void)n_in; (void)out_size;

    cudaLaunchAttribute pdl_attr[1];
    pdl_attr[0].id = cudaLaunchAttributeProgrammaticStreamSerialization;
    pdl_attr[0].val.programmaticStreamSerializationAllowed = 1;

    // k1: plain launch (head of chain)
    k1_colsum_partial<<<dim3(CHUNKS, B_DIM), 128>>>(x);

    // k2a: PDL on k1
    {
        cudaLaunchConfig_t cfg = {};
        cfg.gridDim  = dim3(G2, B_DIM);
        cfg.blockDim = dim3(128);
        cfg.stream   = (cudaStream_t)0;
        cfg.attrs    = pdl_attr;
        cfg.numAttrs = 1;
        cudaLaunchKernelEx(&cfg, k2a_reduce);
    }
    // k2b: PDL on k2a
    {
        cudaLaunchConfig_t cfg = {};
        cfg.gridDim  = dim3(B_DIM);
        cfg.blockDim = dim3(512);
        cfg.stream   = (cudaStream_t)0;
        cfg.attrs    = pdl_attr;
        cfg.numAttrs = 1;
        cudaLaunchKernelEx(&cfg, k2b_finish_and_project, W, pw);
    }
    // k3: PDL on k2b
    {
        cudaLaunchConfig_t cfg = {};
        cfg.gridDim  = dim3((N_DIM * R_DIM / 4) / 256);   // 1024 blocks
        cfg.blockDim = dim3(256);
        cfg.stream   = (cudaStream_t)0;
        cfg.attrs    = pdl_attr;
        cfg.numAttrs = 1;
        cudaLaunchKernelEx(&cfg, k3_broadcast, out4);
    }
}